// round 7
// baseline (speedup 1.0000x reference)
#include <cuda_runtime.h>

#define BB 4
#define CC 64
#define NN 4096
#define KTOP 20
#define NEG (-3.402823466e38f)

// ---- scratch (static __device__ globals; runtime allocation is forbidden) ----
__device__ float g_xt[BB * NN * CC];                 // (B,N,C)  4 MB
__device__ float g_sq[BB * NN];                      // ||x||^2
__device__ float g_pd[(size_t)BB * NN * NN];         // pairwise "distance" 268 MB
__device__ int   g_idx[BB * NN * KTOP];              // top-k indices
__device__ float g_att[BB * NN * CC];                // attention output (B,N,C)
__device__ int   g_M[BB * KTOP];                     // 20 smallest non-local idx per batch
__device__ int   g_boolmode;                         // 0 = 1-byte bool, 1 = int32

// ---------------------------------------------------------------------------
// Detect how the bool mask is packed (1-byte bool vs int32). Deterministic.
// ---------------------------------------------------------------------------
__global__ void detect_bool_kernel(const unsigned char* __restrict__ loc) {
    __shared__ int s;
    if (threadIdx.x == 0) s = 0;
    __syncthreads();
    int any = 0;
    for (int i = threadIdx.x; i < BB * NN; i += blockDim.x)
        if ((i & 3) != 0 && loc[i] != 0) any = 1;
    if (any) atomicOr(&s, 1);
    __syncthreads();
    if (threadIdx.x == 0) g_boolmode = s ? 0 : 1;
}

// ---------------------------------------------------------------------------
// g_M[b][0..19] = the 20 smallest non-local indices of batch b (masked columns
// all take the row-min value, so only their indices matter). One warp/batch.
// ---------------------------------------------------------------------------
__global__ void prep_M_kernel(const void* __restrict__ locraw) {
    int b = threadIdx.x >> 5, lane = threadIdx.x & 31;
    if (b >= BB) return;
    int mode = g_boolmode;
    const unsigned char* loc8  = (const unsigned char*)locraw + b * NN;
    const int*           loc32 = (const int*)locraw + b * NN;
    if (lane < KTOP) g_M[b * KTOP + lane] = 0x7fffffff;
    __syncwarp();
    int count = 0;
    for (int base = 0; base < NN && count < KTOP; base += 32) {
        int j = base + lane;
        bool nl = mode ? (loc32[j] == 0) : (loc8[j] == 0);
        unsigned bal = __ballot_sync(0xffffffffu, nl);
        if (nl) {
            int pos = __popc(bal & ((1u << lane) - 1));
            if (count + pos < KTOP) g_M[b * KTOP + count + pos] = j;
        }
        count += __popc(bal);
    }
}

// ---------------------------------------------------------------------------
// Transpose x (B,C,N) -> g_xt (B,N,C)
// ---------------------------------------------------------------------------
__global__ void transpose_kernel(const float* __restrict__ x) {
    __shared__ float tile[32][33];
    int b = blockIdx.z, c0 = blockIdx.y * 32, n0 = blockIdx.x * 32;
    #pragma unroll
    for (int i = threadIdx.y; i < 32; i += 8)
        tile[i][threadIdx.x] =
            x[((size_t)(b * CC + c0 + i)) * NN + n0 + threadIdx.x];
    __syncthreads();
    #pragma unroll
    for (int i = threadIdx.y; i < 32; i += 8)
        g_xt[((size_t)(b * NN + n0 + i)) * CC + c0 + threadIdx.x] =
            tile[threadIdx.x][i];
}

// ---------------------------------------------------------------------------
// sq: FROZEN — bitwise-matches XLA column-reduce tree (pass depends on it).
// ---------------------------------------------------------------------------
__global__ void sq_kernel(const float* __restrict__ x) {
    int gw   = (blockIdx.x * blockDim.x + threadIdx.x) >> 5;
    int lane = threadIdx.x & 31;
    if (gw >= BB * NN) return;
    int b = gw >> 12;
    int n = gw & (NN - 1);
    const float* xb = x + (size_t)b * CC * NN + n;

    float v0 = xb[(size_t)lane * NN];
    float v1 = xb[(size_t)(lane + 32) * NN];
    float p  = __fadd_rn(__fmul_rn(v0, v0), __fmul_rn(v1, v1));
    p = __fadd_rn(p, __shfl_down_sync(0xffffffffu, p, 16));
    p = __fadd_rn(p, __shfl_down_sync(0xffffffffu, p, 8));
    p = __fadd_rn(p, __shfl_down_sync(0xffffffffu, p, 4));
    p = __fadd_rn(p, __shfl_down_sync(0xffffffffu, p, 2));
    p = __fadd_rn(p, __shfl_down_sync(0xffffffffu, p, 1));
    if (lane == 0) g_sq[gw] = p;
}

// ---------------------------------------------------------------------------
// Pairwise distance GEMM — R4-proven kernel (186us, fma 62%). FROZEN numerics.
// ---------------------------------------------------------------------------
__global__ void __launch_bounds__(256) gemm_kernel(const float* __restrict__ x) {
    __shared__ float As[32][128];
    __shared__ float Bs[32][128];
    int b  = blockIdx.z;
    int ib = blockIdx.y << 7;
    int jb = blockIdx.x << 7;
    int tid = threadIdx.x;
    int tx = tid & 15, ty = tid >> 4;

    const float* xb = x + (size_t)b * CC * NN;

    float acc[8][8];
    #pragma unroll
    for (int i = 0; i < 8; ++i)
        #pragma unroll
        for (int j = 0; j < 8; ++j) acc[i][j] = 0.f;

    for (int k0 = 0; k0 < CC; k0 += 32) {
        if (k0) __syncthreads();
        #pragma unroll
        for (int u = 0; u < 4; ++u) {
            int idx = tid + (u << 8);
            int c = idx >> 5;
            int p = (idx & 31) << 2;
            *(float4*)&As[c][p] = *(const float4*)&xb[(size_t)(k0 + c) * NN + ib + p];
            *(float4*)&Bs[c][p] = *(const float4*)&xb[(size_t)(k0 + c) * NN + jb + p];
        }
        __syncthreads();
        #pragma unroll
        for (int kk = 0; kk < 32; ++kk) {
            float4 a0 = *(float4*)&As[kk][(ty << 2)];
            float4 a1 = *(float4*)&As[kk][64 + (ty << 2)];
            float4 b0 = *(float4*)&Bs[kk][(tx << 2)];
            float4 b1 = *(float4*)&Bs[kk][64 + (tx << 2)];
            float a[8]  = {a0.x, a0.y, a0.z, a0.w, a1.x, a1.y, a1.z, a1.w};
            float bv[8] = {b0.x, b0.y, b0.z, b0.w, b1.x, b1.y, b1.z, b1.w};
            #pragma unroll
            for (int i = 0; i < 8; ++i)
                #pragma unroll
                for (int j = 0; j < 8; ++j)
                    acc[i][j] = fmaf(a[i], bv[j], acc[i][j]);
        }
    }

    int irow[8], jcol[8];
    #pragma unroll
    for (int i = 0; i < 8; ++i)
        irow[i] = ib + ((i < 4) ? (ty << 2) + i : 64 + (ty << 2) + (i - 4));
    #pragma unroll
    for (int j = 0; j < 8; ++j)
        jcol[j] = jb + ((j < 4) ? (tx << 2) + j : 64 + (tx << 2) + (j - 4));

    float sqi[8], sqj[8];
    #pragma unroll
    for (int i = 0; i < 8; ++i) sqi[i] = g_sq[b * NN + irow[i]];
    #pragma unroll
    for (int j = 0; j < 8; ++j) sqj[j] = g_sq[b * NN + jcol[j]];

    #pragma unroll
    for (int i = 0; i < 8; ++i) {
        float* dst = g_pd + ((size_t)(b * NN + irow[i])) * NN;
        float4 v0, v1;
        v0.x = __fsub_rn(__fsub_rn(__fmul_rn(2.f, acc[i][0]), sqi[i]), sqj[0]);
        v0.y = __fsub_rn(__fsub_rn(__fmul_rn(2.f, acc[i][1]), sqi[i]), sqj[1]);
        v0.z = __fsub_rn(__fsub_rn(__fmul_rn(2.f, acc[i][2]), sqi[i]), sqj[2]);
        v0.w = __fsub_rn(__fsub_rn(__fmul_rn(2.f, acc[i][3]), sqi[i]), sqj[3]);
        v1.x = __fsub_rn(__fsub_rn(__fmul_rn(2.f, acc[i][4]), sqi[i]), sqj[4]);
        v1.y = __fsub_rn(__fsub_rn(__fmul_rn(2.f, acc[i][5]), sqi[i]), sqj[5]);
        v1.z = __fsub_rn(__fsub_rn(__fmul_rn(2.f, acc[i][6]), sqi[i]), sqj[6]);
        v1.w = __fsub_rn(__fsub_rn(__fmul_rn(2.f, acc[i][7]), sqi[i]), sqj[7]);
        *(float4*)&dst[jcol[0]] = v0;
        *(float4*)&dst[jcol[4]] = v1;
    }
}

// ---------------------------------------------------------------------------
// SINGLE-PASS top-k: one warp per row, reads pd ONCE (vs twice in R4).
// Per-lane sorted top-20 over LOCAL columns + simultaneous raw row-min,
// 20-round warp merge, then exact merge with (mn, g_M[b]) — R5-proven logic.
// ---------------------------------------------------------------------------
__global__ void __launch_bounds__(256) topk_kernel(const void* __restrict__ locraw) {
    __shared__ float s_v[8][KTOP];
    __shared__ int   s_i[8][KTOP];
    __shared__ int   s_M[KTOP];

    int w    = threadIdx.x >> 5;
    int lane = threadIdx.x & 31;
    int gw   = blockIdx.x * 8 + w;              // row id
    int b    = gw >> 12;

    if (threadIdx.x < KTOP) s_M[threadIdx.x] = g_M[b * KTOP + threadIdx.x];
    __syncthreads();

    const float* row = g_pd + (size_t)gw * NN;
    int mode = g_boolmode;
    const unsigned char* loc8  = (const unsigned char*)locraw + b * NN;
    const int*           loc32 = (const int*)locraw + b * NN;

    float vals[KTOP];
    int   inds[KTOP];
    #pragma unroll
    for (int p = 0; p < KTOP; ++p) { vals[p] = NEG; inds[p] = 0x7fffffff; }

    float mn = 3.402823466e38f;
    for (int t = 0; t < NN / 32; ++t) {
        int j = t * 32 + lane;
        float v = row[j];
        mn = fminf(mn, v);                       // raw min over ALL columns
        bool lc = mode ? (loc32[j] != 0) : (loc8[j] != 0);
        if (lc && (v > vals[KTOP - 1] ||
                   (v == vals[KTOP - 1] && j < inds[KTOP - 1]))) {
            vals[KTOP - 1] = v; inds[KTOP - 1] = j;
            #pragma unroll
            for (int p = KTOP - 1; p > 0; --p) {
                bool sw = (vals[p] > vals[p - 1]) ||
                          (vals[p] == vals[p - 1] && inds[p] < inds[p - 1]);
                if (sw) {
                    float tv = vals[p]; vals[p] = vals[p - 1]; vals[p - 1] = tv;
                    int   ti = inds[p]; inds[p] = inds[p - 1]; inds[p - 1] = ti;
                }
            }
        }
    }
    #pragma unroll
    for (int o = 16; o; o >>= 1)
        mn = fminf(mn, __shfl_xor_sync(0xffffffffu, mn, o));

    // 20 rounds of warp arg-best -> sorted local top-20 into smem
    for (int r = 0; r < KTOP; ++r) {
        float bv = vals[0];
        int   bi = inds[0];
        #pragma unroll
        for (int o = 16; o; o >>= 1) {
            float ov = __shfl_xor_sync(0xffffffffu, bv, o);
            int   oi = __shfl_xor_sync(0xffffffffu, bi, o);
            if (ov > bv || (ov == bv && oi < bi)) { bv = ov; bi = oi; }
        }
        if (lane == 0) { s_v[w][r] = bv; s_i[w][r] = bi; }
        if (bv == vals[0] && bi == inds[0]) {    // winner (indices unique)
            #pragma unroll
            for (int p = 0; p < KTOP - 1; ++p) { vals[p] = vals[p + 1]; inds[p] = inds[p + 1]; }
            vals[KTOP - 1] = NEG;
            inds[KTOP - 1] = 0x7fffffff;
        }
    }
    __syncwarp();

    // exact merge of local list with (mn, M[0..19])
    if (lane == 0) {
        int* dst = g_idx + (size_t)gw * KTOP;
        int pa = 0, pb = 0;
        #pragma unroll
        for (int r = 0; r < KTOP; ++r) {
            float va = s_v[w][pa]; int ia = s_i[w][pa];
            int   ib = s_M[pb];
            float vb = (ib == 0x7fffffff) ? NEG : mn;
            bool tA = (va > vb) || (va == vb && ia < ib);
            dst[r] = tA ? ia : ib;
            if (tA) ++pa; else ++pb;
        }
    }
}

// ---------------------------------------------------------------------------
// attn v2: transposed smem layout s_kT[c][j] (pad 28 -> 16B-aligned rows),
// scores via 4x4 register tiles: 2x LDS.128 per 16 FMA, conflict-free.
// Per-score association UNCHANGED (ascending-c single-acc fma chain) ->
// bitwise-identical output to the R4/R5-passing attn. 4 warps/block.
// ---------------------------------------------------------------------------
__global__ void __launch_bounds__(128) attn_kernel() {
    __shared__ __align__(16) float s_kT[4][CC][28];   // [warp][c][neighbor]
    __shared__ float s_sc[4][KTOP][21];
    __shared__ float s_w [4][KTOP];
    __shared__ int   s_id[4][KTOP];

    int w = threadIdx.x >> 5, lane = threadIdx.x & 31;
    int p = blockIdx.x * 4 + w;
    int b = p >> 12;

    if (lane < KTOP) s_id[w][lane] = g_idx[p * KTOP + lane];
    __syncwarp();

    #pragma unroll 4
    for (int r = 0; r < KTOP; ++r) {
        int id = s_id[w][r];
        const float* src = g_xt + ((size_t)(b * NN + id)) * CC;
        s_kT[w][lane][r]      = src[lane];
        s_kT[w][lane + 32][r] = src[lane + 32];
    }
    __syncwarp();

    // scores: lanes 0..24 each own a 4x4 tile of the 20x20 score matrix
    if (lane < 25) {
        int i0 = (lane / 5) * 4, j0 = (lane % 5) * 4;
        float acc[4][4];
        #pragma unroll
        for (int r = 0; r < 4; ++r)
            #pragma unroll
            for (int s = 0; s < 4; ++s) acc[r][s] = 0.f;
        #pragma unroll 8
        for (int c = 0; c < CC; ++c) {
            float4 a  = *(const float4*)&s_kT[w][c][i0];
            float4 bq = *(const float4*)&s_kT[w][c][j0];
            float av[4] = {a.x, a.y, a.z, a.w};
            float bv[4] = {bq.x, bq.y, bq.z, bq.w};
            #pragma unroll
            for (int r = 0; r < 4; ++r)
                #pragma unroll
                for (int s = 0; s < 4; ++s)
                    acc[r][s] = fmaf(av[r], bv[s], acc[r][s]);
        }
        const float scale = 0.125f;   // 1/sqrt(64)
        #pragma unroll
        for (int r = 0; r < 4; ++r)
            #pragma unroll
            for (int s = 0; s < 4; ++s)
                s_sc[w][i0 + r][j0 + s] = acc[r][s] * scale;
    }
    __syncwarp();

    if (lane < KTOP) {
        float m = NEG;
        #pragma unroll
        for (int j = 0; j < KTOP; ++j) m = fmaxf(m, s_sc[w][lane][j]);
        float e[KTOP];
        float sum = 0.f;
        #pragma unroll
        for (int j = 0; j < KTOP; ++j) { e[j] = expf(s_sc[w][lane][j] - m); sum += e[j]; }
        float inv = 1.f / sum;
        #pragma unroll
        for (int j = 0; j < KTOP; ++j) s_sc[w][lane][j] = e[j] * inv;
    }
    __syncwarp();

    if (lane < KTOP) {
        float a = 0.f;
        #pragma unroll
        for (int i = 0; i < KTOP; ++i) a += s_sc[w][i][lane];
        s_w[w][lane] = a * (1.f / (float)KTOP);
    }
    __syncwarp();

    float acc0 = 0.f, acc1 = 0.f;
    #pragma unroll
    for (int j = 0; j < KTOP; ++j) {
        float wj = s_w[w][j];
        acc0 = fmaf(wj, s_kT[w][lane][j],      acc0);
        acc1 = fmaf(wj, s_kT[w][lane + 32][j], acc1);
    }
    g_att[(size_t)p * CC + lane]      = acc0;
    g_att[(size_t)p * CC + lane + 32] = acc1;
}

// ---------------------------------------------------------------------------
// Feature assembly: block = 64 points, att gathers staged through smem in
// 8-channel chunks (g_att 4MB -> L2), fully-coalesced 5KB contiguous stores.
// ---------------------------------------------------------------------------
__global__ void __launch_bounds__(256) feat_kernel(const float* __restrict__ x,
                                                   float* __restrict__ out) {
    __shared__ int   s_nb[64 * KTOP];       // 5 KB
    __shared__ float s_att[64 * KTOP][8];   // 40 KB
    __shared__ float s_x[8][64];            // 2 KB

    int b  = blockIdx.y;
    int n0 = blockIdx.x << 6;
    int tid = threadIdx.x;

    for (int e = tid; e < 64 * KTOP; e += 256)
        s_nb[e] = g_idx[((size_t)(b * NN + n0)) * KTOP + e];
    __syncthreads();

    const float* attb = g_att + (size_t)b * NN * CC;
    const float* xb   = x + (size_t)b * CC * NN;
    const size_t outb = ((size_t)b * 2 * CC) * NN * KTOP;

    for (int c0 = 0; c0 < 2 * CC; c0 += 8) {
        __syncthreads();                      // prev chunk readers done
        bool firstHalf = (c0 < CC);
        int cx = firstHalf ? c0 : (c0 - CC);
        for (int e = tid; e < 8 * 64; e += 256) {
            int r = e >> 6, p = e & 63;
            s_x[r][p] = xb[(size_t)(cx + r) * NN + n0 + p];
        }
        if (firstHalf) {
            for (int e = tid; e < 64 * KTOP; e += 256) {
                int nb = s_nb[e];
                const float* src = attb + (size_t)nb * CC + c0;
                *(float4*)&s_att[e][0] = *(const float4*)(src);
                *(float4*)&s_att[e][4] = *(const float4*)(src + 4);
            }
        }
        __syncthreads();
        #pragma unroll
        for (int cc = 0; cc < 8; ++cc) {
            int c2 = c0 + cc;
            float* dst = out + outb + ((size_t)c2 * NN + n0) * KTOP;
            for (int e = tid; e < 64 * KTOP; e += 256) {
                int dn = e / KTOP;
                float v = firstHalf ? (s_att[e][cc] - s_x[cc][dn]) : s_x[cc][dn];
                dst[e] = v;
            }
        }
    }

    // idx_flat tail
    const size_t FEAT = (size_t)BB * 2 * CC * NN * KTOP;
    for (int e = tid; e < 64 * KTOP; e += 256)
        out[FEAT + ((size_t)(b * NN + n0)) * KTOP + e] = (float)(s_nb[e] + b * NN);
}

// ---------------------------------------------------------------------------
extern "C" void kernel_launch(void* const* d_in, const int* in_sizes, int n_in,
                              void* d_out, int out_size) {
    (void)in_sizes; (void)n_in; (void)out_size;
    const float* x  = (const float*)d_in[0];
    const void* loc = d_in[1];          // bool mask (packing auto-detected)
    float* out = (float*)d_out;

    detect_bool_kernel<<<1, 256>>>((const unsigned char*)loc);
    prep_M_kernel<<<1, 128>>>(loc);
    transpose_kernel<<<dim3(NN / 32, CC / 32, BB), dim3(32, 8)>>>(x);
    sq_kernel<<<(BB * NN * 32) / 256, 256>>>(x);
    gemm_kernel<<<dim3(NN / 128, NN / 128, BB), 256>>>(x);
    topk_kernel<<<(BB * NN) / 8, 256>>>(loc);
    attn_kernel<<<(BB * NN) / 4, 128>>>();
    feat_kernel<<<dim3(NN / 64, BB), 256>>>(x, out);
}

// round 9
// speedup vs baseline: 1.4940x; 1.4940x over previous
#include <cuda_runtime.h>

#define BB 4
#define CC 64
#define NN 4096
#define KTOP 20
#define NEG (-3.402823466e38f)

// ---- scratch (static __device__ globals; runtime allocation is forbidden) ----
__device__ float g_xt[BB * NN * CC];                 // (B,N,C)  4 MB
__device__ float g_sq[BB * NN];                      // ||x||^2
__device__ float g_pd[(size_t)BB * NN * NN];         // pairwise "distance" 268 MB
__device__ int   g_idx[BB * NN * KTOP];              // top-k indices
__device__ float g_att[BB * NN * CC];                // attention output (B,N,C)
__device__ int   g_M[BB * KTOP];                     // 20 smallest non-local idx per batch
__device__ int   g_boolmode;                         // 0 = 1-byte bool, 1 = int32

// ---------------------------------------------------------------------------
// Combined: detect bool packing (1-byte vs int32) + per-batch M-list
// (20 smallest non-local indices; masked columns all take the row-min value,
// so only their indices matter). One block.
// ---------------------------------------------------------------------------
__global__ void prep_kernel(const unsigned char* __restrict__ loc) {
    __shared__ int s;
    if (threadIdx.x == 0) s = 0;
    __syncthreads();
    int any = 0;
    for (int i = threadIdx.x; i < BB * NN; i += blockDim.x)
        if ((i & 3) != 0 && loc[i] != 0) any = 1;
    if (any) atomicOr(&s, 1);
    __syncthreads();
    int mode = s ? 0 : 1;                            // 1 = int32 layout
    if (threadIdx.x == 0) g_boolmode = mode;

    int b = threadIdx.x >> 5, lane = threadIdx.x & 31;
    if (b < BB) {
        const unsigned char* loc8  = loc + b * NN;
        const int*           loc32 = (const int*)loc + b * NN;
        if (lane < KTOP) g_M[b * KTOP + lane] = 0x7fffffff;
        __syncwarp();
        int count = 0;
        for (int base = 0; base < NN && count < KTOP; base += 32) {
            int j = base + lane;
            bool nl = mode ? (loc32[j] == 0) : (loc8[j] == 0);
            unsigned bal = __ballot_sync(0xffffffffu, nl);
            if (nl) {
                int pos = __popc(bal & ((1u << lane) - 1));
                if (count + pos < KTOP) g_M[b * KTOP + count + pos] = j;
            }
            count += __popc(bal);
        }
    }
}

// ---------------------------------------------------------------------------
// sq: FROZEN — bitwise-matches XLA column-reduce tree (pass depends on it).
// ---------------------------------------------------------------------------
__global__ void sq_kernel(const float* __restrict__ x) {
    int gw   = (blockIdx.x * blockDim.x + threadIdx.x) >> 5;
    int lane = threadIdx.x & 31;
    if (gw >= BB * NN) return;
    int b = gw >> 12;
    int n = gw & (NN - 1);
    const float* xb = x + (size_t)b * CC * NN + n;

    float v0 = xb[(size_t)lane * NN];
    float v1 = xb[(size_t)(lane + 32) * NN];
    float p  = __fadd_rn(__fmul_rn(v0, v0), __fmul_rn(v1, v1));
    p = __fadd_rn(p, __shfl_down_sync(0xffffffffu, p, 16));
    p = __fadd_rn(p, __shfl_down_sync(0xffffffffu, p, 8));
    p = __fadd_rn(p, __shfl_down_sync(0xffffffffu, p, 4));
    p = __fadd_rn(p, __shfl_down_sync(0xffffffffu, p, 2));
    p = __fadd_rn(p, __shfl_down_sync(0xffffffffu, p, 1));
    if (lane == 0) g_sq[gw] = p;
}

// ---------------------------------------------------------------------------
// Pairwise distance GEMM — R4-proven kernel (186us, fma 62%). FROZEN numerics.
// ---------------------------------------------------------------------------
__global__ void __launch_bounds__(256) gemm_kernel(const float* __restrict__ x) {
    __shared__ float As[32][128];
    __shared__ float Bs[32][128];
    int b  = blockIdx.z;
    int ib = blockIdx.y << 7;
    int jb = blockIdx.x << 7;
    int tid = threadIdx.x;
    int tx = tid & 15, ty = tid >> 4;

    const float* xb = x + (size_t)b * CC * NN;

    float acc[8][8];
    #pragma unroll
    for (int i = 0; i < 8; ++i)
        #pragma unroll
        for (int j = 0; j < 8; ++j) acc[i][j] = 0.f;

    for (int k0 = 0; k0 < CC; k0 += 32) {
        if (k0) __syncthreads();
        #pragma unroll
        for (int u = 0; u < 4; ++u) {
            int idx = tid + (u << 8);
            int c = idx >> 5;
            int p = (idx & 31) << 2;
            *(float4*)&As[c][p] = *(const float4*)&xb[(size_t)(k0 + c) * NN + ib + p];
            *(float4*)&Bs[c][p] = *(const float4*)&xb[(size_t)(k0 + c) * NN + jb + p];
        }
        __syncthreads();
        #pragma unroll
        for (int kk = 0; kk < 32; ++kk) {
            float4 a0 = *(float4*)&As[kk][(ty << 2)];
            float4 a1 = *(float4*)&As[kk][64 + (ty << 2)];
            float4 b0 = *(float4*)&Bs[kk][(tx << 2)];
            float4 b1 = *(float4*)&Bs[kk][64 + (tx << 2)];
            float a[8]  = {a0.x, a0.y, a0.z, a0.w, a1.x, a1.y, a1.z, a1.w};
            float bv[8] = {b0.x, b0.y, b0.z, b0.w, b1.x, b1.y, b1.z, b1.w};
            #pragma unroll
            for (int i = 0; i < 8; ++i)
                #pragma unroll
                for (int j = 0; j < 8; ++j)
                    acc[i][j] = fmaf(a[i], bv[j], acc[i][j]);
        }
    }

    int irow[8], jcol[8];
    #pragma unroll
    for (int i = 0; i < 8; ++i)
        irow[i] = ib + ((i < 4) ? (ty << 2) + i : 64 + (ty << 2) + (i - 4));
    #pragma unroll
    for (int j = 0; j < 8; ++j)
        jcol[j] = jb + ((j < 4) ? (tx << 2) + j : 64 + (tx << 2) + (j - 4));

    float sqi[8], sqj[8];
    #pragma unroll
    for (int i = 0; i < 8; ++i) sqi[i] = g_sq[b * NN + irow[i]];
    #pragma unroll
    for (int j = 0; j < 8; ++j) sqj[j] = g_sq[b * NN + jcol[j]];

    #pragma unroll
    for (int i = 0; i < 8; ++i) {
        float* dst = g_pd + ((size_t)(b * NN + irow[i])) * NN;
        float4 v0, v1;
        v0.x = __fsub_rn(__fsub_rn(__fmul_rn(2.f, acc[i][0]), sqi[i]), sqj[0]);
        v0.y = __fsub_rn(__fsub_rn(__fmul_rn(2.f, acc[i][1]), sqi[i]), sqj[1]);
        v0.z = __fsub_rn(__fsub_rn(__fmul_rn(2.f, acc[i][2]), sqi[i]), sqj[2]);
        v0.w = __fsub_rn(__fsub_rn(__fmul_rn(2.f, acc[i][3]), sqi[i]), sqj[3]);
        v1.x = __fsub_rn(__fsub_rn(__fmul_rn(2.f, acc[i][4]), sqi[i]), sqj[4]);
        v1.y = __fsub_rn(__fsub_rn(__fmul_rn(2.f, acc[i][5]), sqi[i]), sqj[5]);
        v1.z = __fsub_rn(__fsub_rn(__fmul_rn(2.f, acc[i][6]), sqi[i]), sqj[6]);
        v1.w = __fsub_rn(__fsub_rn(__fmul_rn(2.f, acc[i][7]), sqi[i]), sqj[7]);
        *(float4*)&dst[jcol[0]] = v0;
        *(float4*)&dst[jcol[4]] = v1;
    }
}

// ---------------------------------------------------------------------------
// SINGLE-PASS top-k: one warp per row, reads pd ONCE.
// Per-lane sorted top-20 over LOCAL columns + simultaneous raw row-min,
// 20-round warp merge, then exact merge with (mn, g_M[b]).
// Placed 4th in the launch sequence so ncu captures it this round.
// ---------------------------------------------------------------------------
__global__ void __launch_bounds__(256) topk_kernel(const void* __restrict__ locraw) {
    __shared__ float s_v[8][KTOP];
    __shared__ int   s_i[8][KTOP];
    __shared__ int   s_M[KTOP];

    int w    = threadIdx.x >> 5;
    int lane = threadIdx.x & 31;
    int gw   = blockIdx.x * 8 + w;              // row id
    int b    = gw >> 12;

    if (threadIdx.x < KTOP) s_M[threadIdx.x] = g_M[b * KTOP + threadIdx.x];
    __syncthreads();

    const float* row = g_pd + (size_t)gw * NN;
    int mode = g_boolmode;
    const unsigned char* loc8  = (const unsigned char*)locraw + b * NN;
    const int*           loc32 = (const int*)locraw + b * NN;

    float vals[KTOP];
    int   inds[KTOP];
    #pragma unroll
    for (int p = 0; p < KTOP; ++p) { vals[p] = NEG; inds[p] = 0x7fffffff; }

    float mn = 3.402823466e38f;
    for (int t = 0; t < NN / 32; ++t) {
        int j = t * 32 + lane;
        float v = row[j];
        mn = fminf(mn, v);                       // raw min over ALL columns
        bool lc = mode ? (loc32[j] != 0) : (loc8[j] != 0);
        if (lc && (v > vals[KTOP - 1] ||
                   (v == vals[KTOP - 1] && j < inds[KTOP - 1]))) {
            vals[KTOP - 1] = v; inds[KTOP - 1] = j;
            #pragma unroll
            for (int p = KTOP - 1; p > 0; --p) {
                bool sw = (vals[p] > vals[p - 1]) ||
                          (vals[p] == vals[p - 1] && inds[p] < inds[p - 1]);
                if (sw) {
                    float tv = vals[p]; vals[p] = vals[p - 1]; vals[p - 1] = tv;
                    int   ti = inds[p]; inds[p] = inds[p - 1]; inds[p - 1] = ti;
                }
            }
        }
    }
    #pragma unroll
    for (int o = 16; o; o >>= 1)
        mn = fminf(mn, __shfl_xor_sync(0xffffffffu, mn, o));

    // 20 rounds of warp arg-best -> sorted local top-20 into smem
    for (int r = 0; r < KTOP; ++r) {
        float bv = vals[0];
        int   bi = inds[0];
        #pragma unroll
        for (int o = 16; o; o >>= 1) {
            float ov = __shfl_xor_sync(0xffffffffu, bv, o);
            int   oi = __shfl_xor_sync(0xffffffffu, bi, o);
            if (ov > bv || (ov == bv && oi < bi)) { bv = ov; bi = oi; }
        }
        if (lane == 0) { s_v[w][r] = bv; s_i[w][r] = bi; }
        if (bv == vals[0] && bi == inds[0]) {    // winner (indices unique)
            #pragma unroll
            for (int p = 0; p < KTOP - 1; ++p) { vals[p] = vals[p + 1]; inds[p] = inds[p + 1]; }
            vals[KTOP - 1] = NEG;
            inds[KTOP - 1] = 0x7fffffff;
        }
    }
    __syncwarp();

    // exact merge of local list with (mn, M[0..19])
    if (lane == 0) {
        int* dst = g_idx + (size_t)gw * KTOP;
        int pa = 0, pb = 0;
        #pragma unroll
        for (int r = 0; r < KTOP; ++r) {
            float va = s_v[w][pa]; int ia = s_i[w][pa];
            int   ib = s_M[pb];
            float vb = (ib == 0x7fffffff) ? NEG : mn;
            bool tA = (va > vb) || (va == vb && ia < ib);
            dst[r] = tA ? ia : ib;
            if (tA) ++pa; else ++pb;
        }
    }
}

// ---------------------------------------------------------------------------
// Transpose x (B,C,N) -> g_xt (B,N,C)  (only needed before attn/feat)
// ---------------------------------------------------------------------------
__global__ void transpose_kernel(const float* __restrict__ x) {
    __shared__ float tile[32][33];
    int b = blockIdx.z, c0 = blockIdx.y * 32, n0 = blockIdx.x * 32;
    #pragma unroll
    for (int i = threadIdx.y; i < 32; i += 8)
        tile[i][threadIdx.x] =
            x[((size_t)(b * CC + c0 + i)) * NN + n0 + threadIdx.x];
    __syncthreads();
    #pragma unroll
    for (int i = threadIdx.y; i < 32; i += 8)
        g_xt[((size_t)(b * NN + n0 + i)) * CC + c0 + threadIdx.x] =
            tile[threadIdx.x][i];
}

// ---------------------------------------------------------------------------
// attn v1 (REVERT — the only never-benched R7 component was attn v2, prime
// regression suspect). One warp per point; numerics frozen.
// ---------------------------------------------------------------------------
__global__ void __launch_bounds__(128) attn_kernel() {
    __shared__ float s_knn[4][KTOP][68];
    __shared__ float s_sc [4][KTOP][21];
    __shared__ float s_w  [4][KTOP];
    __shared__ int   s_id [4][KTOP];

    int w = threadIdx.x >> 5, lane = threadIdx.x & 31;
    int p = blockIdx.x * 4 + w;
    int b = p >> 12;

    if (lane < KTOP) s_id[w][lane] = g_idx[p * KTOP + lane];
    __syncwarp();

    for (int r = 0; r < KTOP; ++r) {
        int id = s_id[w][r];
        const float* src = g_xt + ((size_t)(b * NN + id)) * CC;
        s_knn[w][r][lane]      = src[lane];
        s_knn[w][r][lane + 32] = src[lane + 32];
    }
    __syncwarp();

    const float scale = 0.125f;   // 1/sqrt(64)
    for (int t = 0; t < 13; ++t) {
        int q = lane + t * 32;
        if (q < KTOP * KTOP) {
            int i = q / KTOP, j = q % KTOP;
            float s = 0.f;
            #pragma unroll
            for (int c = 0; c < CC; ++c)
                s = fmaf(s_knn[w][i][c], s_knn[w][j][c], s);
            s_sc[w][i][j] = s * scale;
        }
    }
    __syncwarp();

    if (lane < KTOP) {
        float m = NEG;
        #pragma unroll
        for (int j = 0; j < KTOP; ++j) m = fmaxf(m, s_sc[w][lane][j]);
        float e[KTOP];
        float sum = 0.f;
        #pragma unroll
        for (int j = 0; j < KTOP; ++j) { e[j] = expf(s_sc[w][lane][j] - m); sum += e[j]; }
        float inv = 1.f / sum;
        #pragma unroll
        for (int j = 0; j < KTOP; ++j) s_sc[w][lane][j] = e[j] * inv;
    }
    __syncwarp();

    if (lane < KTOP) {
        float a = 0.f;
        #pragma unroll
        for (int i = 0; i < KTOP; ++i) a += s_sc[w][i][lane];
        s_w[w][lane] = a * (1.f / (float)KTOP);
    }
    __syncwarp();

    float acc0 = 0.f, acc1 = 0.f;
    #pragma unroll
    for (int j = 0; j < KTOP; ++j) {
        float wj = s_w[w][j];
        acc0 = fmaf(wj, s_knn[w][j][lane],      acc0);
        acc1 = fmaf(wj, s_knn[w][j][lane + 32], acc1);
    }
    g_att[(size_t)p * CC + lane]      = acc0;
    g_att[(size_t)p * CC + lane + 32] = acc1;
}

// ---------------------------------------------------------------------------
// Feature assembly v2 (in the 1356us run): block = 64 points, att gathers
// staged through smem in 8-channel chunks, fully-coalesced contiguous stores.
// ---------------------------------------------------------------------------
__global__ void __launch_bounds__(256) feat_kernel(const float* __restrict__ x,
                                                   float* __restrict__ out) {
    __shared__ int   s_nb[64 * KTOP];       // 5 KB
    __shared__ float s_att[64 * KTOP][8];   // 40 KB
    __shared__ float s_x[8][64];            // 2 KB

    int b  = blockIdx.y;
    int n0 = blockIdx.x << 6;
    int tid = threadIdx.x;

    for (int e = tid; e < 64 * KTOP; e += 256)
        s_nb[e] = g_idx[((size_t)(b * NN + n0)) * KTOP + e];
    __syncthreads();

    const float* attb = g_att + (size_t)b * NN * CC;
    const float* xb   = x + (size_t)b * CC * NN;
    const size_t outb = ((size_t)b * 2 * CC) * NN * KTOP;

    for (int c0 = 0; c0 < 2 * CC; c0 += 8) {
        __syncthreads();                      // prev chunk readers done
        bool firstHalf = (c0 < CC);
        int cx = firstHalf ? c0 : (c0 - CC);
        for (int e = tid; e < 8 * 64; e += 256) {
            int r = e >> 6, p = e & 63;
            s_x[r][p] = xb[(size_t)(cx + r) * NN + n0 + p];
        }
        if (firstHalf) {
            for (int e = tid; e < 64 * KTOP; e += 256) {
                int nb = s_nb[e];
                const float* src = attb + (size_t)nb * CC + c0;
                *(float4*)&s_att[e][0] = *(const float4*)(src);
                *(float4*)&s_att[e][4] = *(const float4*)(src + 4);
            }
        }
        __syncthreads();
        #pragma unroll
        for (int cc = 0; cc < 8; ++cc) {
            int c2 = c0 + cc;
            float* dst = out + outb + ((size_t)c2 * NN + n0) * KTOP;
            for (int e = tid; e < 64 * KTOP; e += 256) {
                int dn = e / KTOP;
                float v = firstHalf ? (s_att[e][cc] - s_x[cc][dn]) : s_x[cc][dn];
                dst[e] = v;
            }
        }
    }

    // idx_flat tail
    const size_t FEAT = (size_t)BB * 2 * CC * NN * KTOP;
    for (int e = tid; e < 64 * KTOP; e += 256)
        out[FEAT + ((size_t)(b * NN + n0)) * KTOP + e] = (float)(s_nb[e] + b * NN);
}

// ---------------------------------------------------------------------------
extern "C" void kernel_launch(void* const* d_in, const int* in_sizes, int n_in,
                              void* d_out, int out_size) {
    (void)in_sizes; (void)n_in; (void)out_size;
    const float* x  = (const float*)d_in[0];
    const void* loc = d_in[1];          // bool mask (packing auto-detected)
    float* out = (float*)d_out;

    // Order chosen so topk is the 4th launch (empirically the one ncu captures).
    prep_kernel<<<1, 256>>>((const unsigned char*)loc);
    sq_kernel<<<(BB * NN * 32) / 256, 256>>>(x);
    gemm_kernel<<<dim3(NN / 128, NN / 128, BB), 256>>>(x);
    topk_kernel<<<(BB * NN) / 8, 256>>>(loc);
    transpose_kernel<<<dim3(NN / 32, CC / 32, BB), dim3(32, 8)>>>(x);
    attn_kernel<<<(BB * NN) / 4, 128>>>();
    feat_kernel<<<dim3(NN / 64, BB), 256>>>(x, out);
}

// round 10
// speedup vs baseline: 4.6422x; 3.1072x over previous
#include <cuda_runtime.h>

#define BB 4
#define CC 64
#define NN 4096
#define KTOP 20
#define NEG (-3.402823466e38f)

// ---- scratch (static __device__ globals; runtime allocation is forbidden) ----
__device__ float g_xt[BB * NN * CC];                 // (B,N,C)  4 MB
__device__ float g_sq[BB * NN];                      // ||x||^2
__device__ float g_pd[(size_t)BB * NN * NN];         // pairwise "distance" 268 MB
__device__ int   g_idx[BB * NN * KTOP];              // top-k indices
__device__ float g_att[BB * NN * CC];                // attention output (B,N,C)
__device__ int   g_M[BB * KTOP];                     // 20 smallest non-local idx per batch
__device__ int   g_boolmode;                         // 0 = 1-byte bool, 1 = int32

// ---------------------------------------------------------------------------
// Combined: detect bool packing (1-byte vs int32) + per-batch M-list
// (20 smallest non-local indices). One block.
// ---------------------------------------------------------------------------
__global__ void prep_kernel(const unsigned char* __restrict__ loc) {
    __shared__ int s;
    if (threadIdx.x == 0) s = 0;
    __syncthreads();
    int any = 0;
    for (int i = threadIdx.x; i < BB * NN; i += blockDim.x)
        if ((i & 3) != 0 && loc[i] != 0) any = 1;
    if (any) atomicOr(&s, 1);
    __syncthreads();
    int mode = s ? 0 : 1;                            // 1 = int32 layout
    if (threadIdx.x == 0) g_boolmode = mode;

    int b = threadIdx.x >> 5, lane = threadIdx.x & 31;
    if (b < BB) {
        const unsigned char* loc8  = loc + b * NN;
        const int*           loc32 = (const int*)loc + b * NN;
        if (lane < KTOP) g_M[b * KTOP + lane] = 0x7fffffff;
        __syncwarp();
        int count = 0;
        for (int base = 0; base < NN && count < KTOP; base += 32) {
            int j = base + lane;
            bool nl = mode ? (loc32[j] == 0) : (loc8[j] == 0);
            unsigned bal = __ballot_sync(0xffffffffu, nl);
            if (nl) {
                int pos = __popc(bal & ((1u << lane) - 1));
                if (count + pos < KTOP) g_M[b * KTOP + count + pos] = j;
            }
            count += __popc(bal);
        }
    }
}

// ---------------------------------------------------------------------------
// sq: FROZEN — bitwise-matches XLA column-reduce tree (pass depends on it).
// ---------------------------------------------------------------------------
__global__ void sq_kernel(const float* __restrict__ x) {
    int gw   = (blockIdx.x * blockDim.x + threadIdx.x) >> 5;
    int lane = threadIdx.x & 31;
    if (gw >= BB * NN) return;
    int b = gw >> 12;
    int n = gw & (NN - 1);
    const float* xb = x + (size_t)b * CC * NN + n;

    float v0 = xb[(size_t)lane * NN];
    float v1 = xb[(size_t)(lane + 32) * NN];
    float p  = __fadd_rn(__fmul_rn(v0, v0), __fmul_rn(v1, v1));
    p = __fadd_rn(p, __shfl_down_sync(0xffffffffu, p, 16));
    p = __fadd_rn(p, __shfl_down_sync(0xffffffffu, p, 8));
    p = __fadd_rn(p, __shfl_down_sync(0xffffffffu, p, 4));
    p = __fadd_rn(p, __shfl_down_sync(0xffffffffu, p, 2));
    p = __fadd_rn(p, __shfl_down_sync(0xffffffffu, p, 1));
    if (lane == 0) g_sq[gw] = p;
}

// ---------------------------------------------------------------------------
// Pairwise distance GEMM — R4-proven kernel (186us, fma 62%). FROZEN numerics.
// ---------------------------------------------------------------------------
__global__ void __launch_bounds__(256) gemm_kernel(const float* __restrict__ x) {
    __shared__ float As[32][128];
    __shared__ float Bs[32][128];
    int b  = blockIdx.z;
    int ib = blockIdx.y << 7;
    int jb = blockIdx.x << 7;
    int tid = threadIdx.x;
    int tx = tid & 15, ty = tid >> 4;

    const float* xb = x + (size_t)b * CC * NN;

    float acc[8][8];
    #pragma unroll
    for (int i = 0; i < 8; ++i)
        #pragma unroll
        for (int j = 0; j < 8; ++j) acc[i][j] = 0.f;

    for (int k0 = 0; k0 < CC; k0 += 32) {
        if (k0) __syncthreads();
        #pragma unroll
        for (int u = 0; u < 4; ++u) {
            int idx = tid + (u << 8);
            int c = idx >> 5;
            int p = (idx & 31) << 2;
            *(float4*)&As[c][p] = *(const float4*)&xb[(size_t)(k0 + c) * NN + ib + p];
            *(float4*)&Bs[c][p] = *(const float4*)&xb[(size_t)(k0 + c) * NN + jb + p];
        }
        __syncthreads();
        #pragma unroll
        for (int kk = 0; kk < 32; ++kk) {
            float4 a0 = *(float4*)&As[kk][(ty << 2)];
            float4 a1 = *(float4*)&As[kk][64 + (ty << 2)];
            float4 b0 = *(float4*)&Bs[kk][(tx << 2)];
            float4 b1 = *(float4*)&Bs[kk][64 + (tx << 2)];
            float a[8]  = {a0.x, a0.y, a0.z, a0.w, a1.x, a1.y, a1.z, a1.w};
            float bv[8] = {b0.x, b0.y, b0.z, b0.w, b1.x, b1.y, b1.z, b1.w};
            #pragma unroll
            for (int i = 0; i < 8; ++i)
                #pragma unroll
                for (int j = 0; j < 8; ++j)
                    acc[i][j] = fmaf(a[i], bv[j], acc[i][j]);
        }
    }

    int irow[8], jcol[8];
    #pragma unroll
    for (int i = 0; i < 8; ++i)
        irow[i] = ib + ((i < 4) ? (ty << 2) + i : 64 + (ty << 2) + (i - 4));
    #pragma unroll
    for (int j = 0; j < 8; ++j)
        jcol[j] = jb + ((j < 4) ? (tx << 2) + j : 64 + (tx << 2) + (j - 4));

    float sqi[8], sqj[8];
    #pragma unroll
    for (int i = 0; i < 8; ++i) sqi[i] = g_sq[b * NN + irow[i]];
    #pragma unroll
    for (int j = 0; j < 8; ++j) sqj[j] = g_sq[b * NN + jcol[j]];

    #pragma unroll
    for (int i = 0; i < 8; ++i) {
        float* dst = g_pd + ((size_t)(b * NN + irow[i])) * NN;
        float4 v0, v1;
        v0.x = __fsub_rn(__fsub_rn(__fmul_rn(2.f, acc[i][0]), sqi[i]), sqj[0]);
        v0.y = __fsub_rn(__fsub_rn(__fmul_rn(2.f, acc[i][1]), sqi[i]), sqj[1]);
        v0.z = __fsub_rn(__fsub_rn(__fmul_rn(2.f, acc[i][2]), sqi[i]), sqj[2]);
        v0.w = __fsub_rn(__fsub_rn(__fmul_rn(2.f, acc[i][3]), sqi[i]), sqj[3]);
        v1.x = __fsub_rn(__fsub_rn(__fmul_rn(2.f, acc[i][4]), sqi[i]), sqj[4]);
        v1.y = __fsub_rn(__fsub_rn(__fmul_rn(2.f, acc[i][5]), sqi[i]), sqj[5]);
        v1.z = __fsub_rn(__fsub_rn(__fmul_rn(2.f, acc[i][6]), sqi[i]), sqj[6]);
        v1.w = __fsub_rn(__fsub_rn(__fmul_rn(2.f, acc[i][7]), sqi[i]), sqj[7]);
        *(float4*)&dst[jcol[0]] = v0;
        *(float4*)&dst[jcol[4]] = v1;
    }
}

// ---------------------------------------------------------------------------
// topk v3: warp-collective threshold top-k. One warp per row.
// Top-20 list lives DISTRIBUTED across lanes 0..19, sorted best-first
// (value desc, index asc). A column is a candidate only if it beats the
// warp-global 20th element -> ~113 insertion events/row (vs ~1400 per-lane
// inserts in v2). Each event: ballot -> ffs position -> shfl_up shift.
// Produces the EXACT lexicographic top-20 (insert order cannot change the
// final sorted set), so selection semantics are bit-identical to v2.
// Mask staged as a 128-word smem bitmask (block rows share the batch).
// ---------------------------------------------------------------------------
__global__ void __launch_bounds__(256) topk_kernel(const void* __restrict__ locraw) {
    __shared__ unsigned s_mask[128];
    __shared__ float s_v[8][KTOP];
    __shared__ int   s_i[8][KTOP];
    __shared__ int   s_M[KTOP];

    int tid  = threadIdx.x;
    int w    = tid >> 5;
    int lane = tid & 31;
    int gw   = blockIdx.x * 8 + w;              // row id; all rows same batch
    int b    = gw >> 12;

    int mode = g_boolmode;
    {
        const unsigned char* loc8  = (const unsigned char*)locraw + b * NN;
        const int*           loc32 = (const int*)locraw + b * NN;
        #pragma unroll
        for (int k = 0; k < 16; ++k) {          // 256 cols per pass
            int col = k * 256 + tid;
            bool lc = mode ? (loc32[col] != 0) : (loc8[col] != 0);
            unsigned word = __ballot_sync(0xffffffffu, lc);
            if (lane == 0) s_mask[k * 8 + w] = word;
        }
    }
    if (tid < KTOP) s_M[tid] = g_M[b * KTOP + tid];
    __syncthreads();

    const float4* row4 = (const float4*)(g_pd + (size_t)gw * NN);

    float Lv = NEG;  int Li = 0x7fffffff;       // my slot of the sorted list
    float thv = NEG; int thi = 0x7fffffff;      // 20th element (threshold)
    float mn = 3.402823466e38f;

    for (int t = 0; t < 32; ++t) {
        float4 vv = row4[t * 32 + lane];
        float ve[4] = {vv.x, vv.y, vv.z, vv.w};
        mn = fminf(mn, fminf(fminf(ve[0], ve[1]), fminf(ve[2], ve[3])));
        unsigned wrd = s_mask[t * 4 + (lane >> 3)];
        #pragma unroll
        for (int e = 0; e < 4; ++e) {
            int j = t * 128 + lane * 4 + e;
            bool lc = (wrd >> (((lane & 7) << 2) + e)) & 1u;
            bool q = lc && (ve[e] > thv || (ve[e] == thv && j < thi));
            unsigned cand = __ballot_sync(0xffffffffu, q);
            while (cand) {
                int   src = __ffs(cand) - 1;
                float cv  = __shfl_sync(0xffffffffu, ve[e], src);
                int   cj  = t * 128 + src * 4 + e;
                bool beats = (cv > Lv) || (cv == Lv && cj < Li);
                unsigned bb = __ballot_sync(0xffffffffu, beats) & 0xFFFFFu;
                int pos = __ffs(bb) - 1;        // qualify guarantees bit19 set
                float pv = __shfl_up_sync(0xffffffffu, Lv, 1);
                int   pi = __shfl_up_sync(0xffffffffu, Li, 1);
                if (lane > pos)  { Lv = pv; Li = pi; }
                if (lane == pos) { Lv = cv; Li = cj; }
                thv = __shfl_sync(0xffffffffu, Lv, KTOP - 1);
                thi = __shfl_sync(0xffffffffu, Li, KTOP - 1);
                cand &= ~(1u << src);
                if (cand) {                     // recheck survivors vs new thr
                    bool q2 = ((cand >> lane) & 1u) &&
                              (ve[e] > thv || (ve[e] == thv && j < thi));
                    cand = __ballot_sync(0xffffffffu, q2);
                }
            }
        }
    }
    #pragma unroll
    for (int o = 16; o; o >>= 1)
        mn = fminf(mn, __shfl_xor_sync(0xffffffffu, mn, o));

    if (lane < KTOP) { s_v[w][lane] = Lv; s_i[w][lane] = Li; }
    __syncwarp();

    // exact merge of local list with (mn, M[0..19])
    if (lane == 0) {
        int* dst = g_idx + (size_t)gw * KTOP;
        int pa = 0, pb = 0;
        #pragma unroll
        for (int r = 0; r < KTOP; ++r) {
            float va = s_v[w][pa]; int ia = s_i[w][pa];
            int   ib = s_M[pb];
            float vb = (ib == 0x7fffffff) ? NEG : mn;
            bool tA = (va > vb) || (va == vb && ia < ib);
            dst[r] = tA ? ia : ib;
            if (tA) ++pa; else ++pb;
        }
    }
}

// ---------------------------------------------------------------------------
// Transpose x (B,C,N) -> g_xt (B,N,C)  (only needed before attn/feat)
// ---------------------------------------------------------------------------
__global__ void transpose_kernel(const float* __restrict__ x) {
    __shared__ float tile[32][33];
    int b = blockIdx.z, c0 = blockIdx.y * 32, n0 = blockIdx.x * 32;
    #pragma unroll
    for (int i = threadIdx.y; i < 32; i += 8)
        tile[i][threadIdx.x] =
            x[((size_t)(b * CC + c0 + i)) * NN + n0 + threadIdx.x];
    __syncthreads();
    #pragma unroll
    for (int i = threadIdx.y; i < 32; i += 8)
        g_xt[((size_t)(b * NN + n0 + i)) * CC + c0 + threadIdx.x] =
            tile[threadIdx.x][i];
}

// ---------------------------------------------------------------------------
// attn v1 (proven in both passing runs). One warp per point; numerics frozen.
// ---------------------------------------------------------------------------
__global__ void __launch_bounds__(128) attn_kernel() {
    __shared__ float s_knn[4][KTOP][68];
    __shared__ float s_sc [4][KTOP][21];
    __shared__ float s_w  [4][KTOP];
    __shared__ int   s_id [4][KTOP];

    int w = threadIdx.x >> 5, lane = threadIdx.x & 31;
    int p = blockIdx.x * 4 + w;
    int b = p >> 12;

    if (lane < KTOP) s_id[w][lane] = g_idx[p * KTOP + lane];
    __syncwarp();

    for (int r = 0; r < KTOP; ++r) {
        int id = s_id[w][r];
        const float* src = g_xt + ((size_t)(b * NN + id)) * CC;
        s_knn[w][r][lane]      = src[lane];
        s_knn[w][r][lane + 32] = src[lane + 32];
    }
    __syncwarp();

    const float scale = 0.125f;   // 1/sqrt(64)
    for (int t = 0; t < 13; ++t) {
        int q = lane + t * 32;
        if (q < KTOP * KTOP) {
            int i = q / KTOP, j = q % KTOP;
            float s = 0.f;
            #pragma unroll
            for (int c = 0; c < CC; ++c)
                s = fmaf(s_knn[w][i][c], s_knn[w][j][c], s);
            s_sc[w][i][j] = s * scale;
        }
    }
    __syncwarp();

    if (lane < KTOP) {
        float m = NEG;
        #pragma unroll
        for (int j = 0; j < KTOP; ++j) m = fmaxf(m, s_sc[w][lane][j]);
        float e[KTOP];
        float sum = 0.f;
        #pragma unroll
        for (int j = 0; j < KTOP; ++j) { e[j] = expf(s_sc[w][lane][j] - m); sum += e[j]; }
        float inv = 1.f / sum;
        #pragma unroll
        for (int j = 0; j < KTOP; ++j) s_sc[w][lane][j] = e[j] * inv;
    }
    __syncwarp();

    if (lane < KTOP) {
        float a = 0.f;
        #pragma unroll
        for (int i = 0; i < KTOP; ++i) a += s_sc[w][i][lane];
        s_w[w][lane] = a * (1.f / (float)KTOP);
    }
    __syncwarp();

    float acc0 = 0.f, acc1 = 0.f;
    #pragma unroll
    for (int j = 0; j < KTOP; ++j) {
        float wj = s_w[w][j];
        acc0 = fmaf(wj, s_knn[w][j][lane],      acc0);
        acc1 = fmaf(wj, s_knn[w][j][lane + 32], acc1);
    }
    g_att[(size_t)p * CC + lane]      = acc0;
    g_att[(size_t)p * CC + lane + 32] = acc1;
}

// ---------------------------------------------------------------------------
// Feature assembly v2 (proven): block = 64 points, att gathers staged through
// smem in 8-channel chunks, fully-coalesced contiguous stores.
// ---------------------------------------------------------------------------
__global__ void __launch_bounds__(256) feat_kernel(const float* __restrict__ x,
                                                   float* __restrict__ out) {
    __shared__ int   s_nb[64 * KTOP];       // 5 KB
    __shared__ float s_att[64 * KTOP][8];   // 40 KB
    __shared__ float s_x[8][64];            // 2 KB

    int b  = blockIdx.y;
    int n0 = blockIdx.x << 6;
    int tid = threadIdx.x;

    for (int e = tid; e < 64 * KTOP; e += 256)
        s_nb[e] = g_idx[((size_t)(b * NN + n0)) * KTOP + e];
    __syncthreads();

    const float* attb = g_att + (size_t)b * NN * CC;
    const float* xb   = x + (size_t)b * CC * NN;
    const size_t outb = ((size_t)b * 2 * CC) * NN * KTOP;

    for (int c0 = 0; c0 < 2 * CC; c0 += 8) {
        __syncthreads();                      // prev chunk readers done
        bool firstHalf = (c0 < CC);
        int cx = firstHalf ? c0 : (c0 - CC);
        for (int e = tid; e < 8 * 64; e += 256) {
            int r = e >> 6, p = e & 63;
            s_x[r][p] = xb[(size_t)(cx + r) * NN + n0 + p];
        }
        if (firstHalf) {
            for (int e = tid; e < 64 * KTOP; e += 256) {
                int nb = s_nb[e];
                const float* src = attb + (size_t)nb * CC + c0;
                *(float4*)&s_att[e][0] = *(const float4*)(src);
                *(float4*)&s_att[e][4] = *(const float4*)(src + 4);
            }
        }
        __syncthreads();
        #pragma unroll
        for (int cc = 0; cc < 8; ++cc) {
            int c2 = c0 + cc;
            float* dst = out + outb + ((size_t)c2 * NN + n0) * KTOP;
            for (int e = tid; e < 64 * KTOP; e += 256) {
                int dn = e / KTOP;
                float v = firstHalf ? (s_att[e][cc] - s_x[cc][dn]) : s_x[cc][dn];
                dst[e] = v;
            }
        }
    }

    // idx_flat tail
    const size_t FEAT = (size_t)BB * 2 * CC * NN * KTOP;
    for (int e = tid; e < 64 * KTOP; e += 256)
        out[FEAT + ((size_t)(b * NN + n0)) * KTOP + e] = (float)(s_nb[e] + b * NN);
}

// ---------------------------------------------------------------------------
extern "C" void kernel_launch(void* const* d_in, const int* in_sizes, int n_in,
                              void* d_out, int out_size) {
    (void)in_sizes; (void)n_in; (void)out_size;
    const float* x  = (const float*)d_in[0];
    const void* loc = d_in[1];          // bool mask (packing auto-detected)
    float* out = (float*)d_out;

    // topk kept 4th so the capture verifies the rewrite.
    prep_kernel<<<1, 256>>>((const unsigned char*)loc);
    sq_kernel<<<(BB * NN * 32) / 256, 256>>>(x);
    gemm_kernel<<<dim3(NN / 128, NN / 128, BB), 256>>>(x);
    topk_kernel<<<(BB * NN) / 8, 256>>>(loc);
    transpose_kernel<<<dim3(NN / 32, CC / 32, BB), dim3(32, 8)>>>(x);
    attn_kernel<<<(BB * NN) / 4, 128>>>();
    feat_kernel<<<dim3(NN / 64, BB), 256>>>(x, out);
}

// round 12
// speedup vs baseline: 4.7102x; 1.0147x over previous
#include <cuda_runtime.h>

#define BB 4
#define CC 64
#define NN 4096
#define KTOP 20
#define NEG (-3.402823466e38f)

// ---- scratch (static __device__ globals; runtime allocation is forbidden) ----
__device__ float g_xt[BB * NN * CC];                 // (B,N,C)  4 MB
__device__ float g_sq[BB * NN];                      // ||x||^2
__device__ float g_pd[(size_t)BB * NN * NN];         // pairwise "distance" 268 MB
__device__ int   g_idx[BB * NN * KTOP];              // top-k indices
__device__ float g_att[BB * NN * CC];                // attention output (B,N,C)
__device__ int   g_M[BB * KTOP];                     // 20 smallest non-local idx per batch
__device__ int   g_boolmode;                         // 0 = 1-byte bool, 1 = int32

// ---------------------------------------------------------------------------
// pre_kernel: role-dispatched fusion of sq (blocks 0..2047), prep (block 2048),
// transpose (blocks 2049..3072). All three are independent.
// ---------------------------------------------------------------------------
__global__ void __launch_bounds__(256) pre_kernel(const float* __restrict__ x,
                                                  const unsigned char* __restrict__ loc) {
    __shared__ float tile[32][33];
    __shared__ int   s;
    int blk = blockIdx.x;
    int tid = threadIdx.x;

    if (blk < 2048) {
        // ---- sq role: FROZEN XLA column-reduce tree ----
        int gw   = (blk * 256 + tid) >> 5;
        int lane = tid & 31;
        int b = gw >> 12;
        int n = gw & (NN - 1);
        const float* xb = x + (size_t)b * CC * NN + n;
        float v0 = xb[(size_t)lane * NN];
        float v1 = xb[(size_t)(lane + 32) * NN];
        float p  = __fadd_rn(__fmul_rn(v0, v0), __fmul_rn(v1, v1));
        p = __fadd_rn(p, __shfl_down_sync(0xffffffffu, p, 16));
        p = __fadd_rn(p, __shfl_down_sync(0xffffffffu, p, 8));
        p = __fadd_rn(p, __shfl_down_sync(0xffffffffu, p, 4));
        p = __fadd_rn(p, __shfl_down_sync(0xffffffffu, p, 2));
        p = __fadd_rn(p, __shfl_down_sync(0xffffffffu, p, 1));
        if (lane == 0) g_sq[gw] = p;
    } else if (blk == 2048) {
        // ---- prep role: detect bool packing + per-batch M-list ----
        if (tid == 0) s = 0;
        __syncthreads();
        int any = 0;
        for (int i = tid; i < BB * NN; i += 256)
            if ((i & 3) != 0 && loc[i] != 0) any = 1;
        if (any) atomicOr(&s, 1);
        __syncthreads();
        int mode = s ? 0 : 1;                        // 1 = int32 layout
        if (tid == 0) g_boolmode = mode;

        int b = tid >> 5, lane = tid & 31;
        if (b < BB) {
            const unsigned char* loc8  = loc + b * NN;
            const int*           loc32 = (const int*)loc + b * NN;
            if (lane < KTOP) g_M[b * KTOP + lane] = 0x7fffffff;
            __syncwarp();
            int count = 0;
            for (int base = 0; base < NN && count < KTOP; base += 32) {
                int j = base + lane;
                bool nl = mode ? (loc32[j] == 0) : (loc8[j] == 0);
                unsigned bal = __ballot_sync(0xffffffffu, nl);
                if (nl) {
                    int pos = __popc(bal & ((1u << lane) - 1));
                    if (count + pos < KTOP) g_M[b * KTOP + count + pos] = j;
                }
                count += __popc(bal);
            }
        }
    } else {
        // ---- transpose role: x (B,C,N) -> g_xt (B,N,C) ----
        int idx = blk - 2049;                        // 0..1023
        int n0 = (idx & 127) * 32;
        int c0 = ((idx >> 7) & 1) * 32;
        int b  = idx >> 8;
        int tx = tid & 31, ty = tid >> 5;
        #pragma unroll
        for (int i = ty; i < 32; i += 8)
            tile[i][tx] = x[((size_t)(b * CC + c0 + i)) * NN + n0 + tx];
        __syncthreads();
        #pragma unroll
        for (int i = ty; i < 32; i += 8)
            g_xt[((size_t)(b * NN + n0 + i)) * CC + c0 + tx] = tile[tx][i];
    }
}

// ---------------------------------------------------------------------------
// Pairwise distance GEMM — R4-proven kernel (186us, fma 62%). FROZEN numerics.
// ---------------------------------------------------------------------------
__global__ void __launch_bounds__(256) gemm_kernel(const float* __restrict__ x) {
    __shared__ float As[32][128];
    __shared__ float Bs[32][128];
    int b  = blockIdx.z;
    int ib = blockIdx.y << 7;
    int jb = blockIdx.x << 7;
    int tid = threadIdx.x;
    int tx = tid & 15, ty = tid >> 4;

    const float* xb = x + (size_t)b * CC * NN;

    float acc[8][8];
    #pragma unroll
    for (int i = 0; i < 8; ++i)
        #pragma unroll
        for (int j = 0; j < 8; ++j) acc[i][j] = 0.f;

    for (int k0 = 0; k0 < CC; k0 += 32) {
        if (k0) __syncthreads();
        #pragma unroll
        for (int u = 0; u < 4; ++u) {
            int idx = tid + (u << 8);
            int c = idx >> 5;
            int p = (idx & 31) << 2;
            *(float4*)&As[c][p] = *(const float4*)&xb[(size_t)(k0 + c) * NN + ib + p];
            *(float4*)&Bs[c][p] = *(const float4*)&xb[(size_t)(k0 + c) * NN + jb + p];
        }
        __syncthreads();
        #pragma unroll
        for (int kk = 0; kk < 32; ++kk) {
            float4 a0 = *(float4*)&As[kk][(ty << 2)];
            float4 a1 = *(float4*)&As[kk][64 + (ty << 2)];
            float4 b0 = *(float4*)&Bs[kk][(tx << 2)];
            float4 b1 = *(float4*)&Bs[kk][64 + (tx << 2)];
            float a[8]  = {a0.x, a0.y, a0.z, a0.w, a1.x, a1.y, a1.z, a1.w};
            float bv[8] = {b0.x, b0.y, b0.z, b0.w, b1.x, b1.y, b1.z, b1.w};
            #pragma unroll
            for (int i = 0; i < 8; ++i)
                #pragma unroll
                for (int j = 0; j < 8; ++j)
                    acc[i][j] = fmaf(a[i], bv[j], acc[i][j]);
        }
    }

    int irow[8], jcol[8];
    #pragma unroll
    for (int i = 0; i < 8; ++i)
        irow[i] = ib + ((i < 4) ? (ty << 2) + i : 64 + (ty << 2) + (i - 4));
    #pragma unroll
    for (int j = 0; j < 8; ++j)
        jcol[j] = jb + ((j < 4) ? (tx << 2) + j : 64 + (tx << 2) + (j - 4));

    float sqi[8], sqj[8];
    #pragma unroll
    for (int i = 0; i < 8; ++i) sqi[i] = g_sq[b * NN + irow[i]];
    #pragma unroll
    for (int j = 0; j < 8; ++j) sqj[j] = g_sq[b * NN + jcol[j]];

    #pragma unroll
    for (int i = 0; i < 8; ++i) {
        float* dst = g_pd + ((size_t)(b * NN + irow[i])) * NN;
        float4 v0, v1;
        v0.x = __fsub_rn(__fsub_rn(__fmul_rn(2.f, acc[i][0]), sqi[i]), sqj[0]);
        v0.y = __fsub_rn(__fsub_rn(__fmul_rn(2.f, acc[i][1]), sqi[i]), sqj[1]);
        v0.z = __fsub_rn(__fsub_rn(__fmul_rn(2.f, acc[i][2]), sqi[i]), sqj[2]);
        v0.w = __fsub_rn(__fsub_rn(__fmul_rn(2.f, acc[i][3]), sqi[i]), sqj[3]);
        v1.x = __fsub_rn(__fsub_rn(__fmul_rn(2.f, acc[i][4]), sqi[i]), sqj[4]);
        v1.y = __fsub_rn(__fsub_rn(__fmul_rn(2.f, acc[i][5]), sqi[i]), sqj[5]);
        v1.z = __fsub_rn(__fsub_rn(__fmul_rn(2.f, acc[i][6]), sqi[i]), sqj[6]);
        v1.w = __fsub_rn(__fsub_rn(__fmul_rn(2.f, acc[i][7]), sqi[i]), sqj[7]);
        *(float4*)&dst[jcol[0]] = v0;
        *(float4*)&dst[jcol[4]] = v1;
    }
}

// ---------------------------------------------------------------------------
// topk v3.1: warp-collective threshold top-k, ONE ballot per float4.
// Qualify = warp-max of the 4 masked values >= threshold value (ties over-
// collected, exact lex applied at insert). Sentinel index -1 makes NEG-phase
// tie candidates fail the uniform insert check cheaply. Stale candidates are
// re-balloted after each insert. Exact lexicographic top-20 — selection
// semantics bit-identical to v3.
// ---------------------------------------------------------------------------
__global__ void __launch_bounds__(256) topk_kernel(const void* __restrict__ locraw) {
    __shared__ unsigned s_mask[128];
    __shared__ float s_v[8][KTOP];
    __shared__ int   s_i[8][KTOP];
    __shared__ int   s_M[KTOP];

    int tid  = threadIdx.x;
    int w    = tid >> 5;
    int lane = tid & 31;
    int gw   = blockIdx.x * 8 + w;              // row id; all rows same batch
    int b    = gw >> 12;

    int mode = g_boolmode;
    {
        const unsigned char* loc8  = (const unsigned char*)locraw + b * NN;
        const int*           loc32 = (const int*)locraw + b * NN;
        #pragma unroll
        for (int k = 0; k < 16; ++k) {          // 256 cols per pass
            int col = k * 256 + tid;
            bool lc = mode ? (loc32[col] != 0) : (loc8[col] != 0);
            unsigned word = __ballot_sync(0xffffffffu, lc);
            if (lane == 0) s_mask[k * 8 + w] = word;
        }
    }
    if (tid < KTOP) s_M[tid] = g_M[b * KTOP + tid];
    __syncthreads();

    const float4* row4 = (const float4*)(g_pd + (size_t)gw * NN);

    float Lv = NEG;  int Li = -1;               // list slot; sentinel idx -1
    float thv = NEG; int thi = -1;              // 20th element (threshold)
    float mn = 3.402823466e38f;

    for (int t = 0; t < 32; ++t) {
        float4 vv = row4[t * 32 + lane];
        mn = fminf(mn, fminf(fminf(vv.x, vv.y), fminf(vv.z, vv.w)));
        unsigned wrd = s_mask[t * 4 + (lane >> 3)];
        unsigned nib = (wrd >> ((lane & 7) << 2)) & 0xFu;
        float c0 = (nib & 1u) ? vv.x : NEG;
        float c1 = (nib & 2u) ? vv.y : NEG;
        float c2 = (nib & 4u) ? vv.z : NEG;
        float c3 = (nib & 8u) ? vv.w : NEG;
        float m4 = fmaxf(fmaxf(c0, c1), fmaxf(c2, c3));
        unsigned cand = __ballot_sync(0xffffffffu, m4 >= thv);
        while (cand) {
            int src = __ffs(cand) - 1;
            cand &= cand - 1u;
            float b0 = __shfl_sync(0xffffffffu, c0, src);
            float b1 = __shfl_sync(0xffffffffu, c1, src);
            float b2 = __shfl_sync(0xffffffffu, c2, src);
            float b3 = __shfl_sync(0xffffffffu, c3, src);
            int jb = t * 128 + src * 4;
            #pragma unroll
            for (int e = 0; e < 4; ++e) {
                float cv = (e == 0) ? b0 : (e == 1) ? b1 : (e == 2) ? b2 : b3;
                int   cj = jb + e;
                if (cv > thv || (cv == thv && cj < thi)) {   // warp-uniform
                    bool beats = (cv > Lv) || (cv == Lv && cj < Li);
                    unsigned bb = __ballot_sync(0xffffffffu, beats) & 0xFFFFFu;
                    int pos = __ffs(bb) - 1;    // >=0: beats true at lane 19
                    float pv = __shfl_up_sync(0xffffffffu, Lv, 1);
                    int   pi = __shfl_up_sync(0xffffffffu, Li, 1);
                    if (lane > pos)  { Lv = pv; Li = pi; }
                    if (lane == pos) { Lv = cv; Li = cj; }
                    thv = __shfl_sync(0xffffffffu, Lv, KTOP - 1);
                    thi = __shfl_sync(0xffffffffu, Li, KTOP - 1);
                }
            }
            if (cand)                            // drop stale candidates
                cand = __ballot_sync(0xffffffffu,
                                     ((cand >> lane) & 1u) && (m4 >= thv));
        }
    }
    #pragma unroll
    for (int o = 16; o; o >>= 1)
        mn = fminf(mn, __shfl_xor_sync(0xffffffffu, mn, o));

    if (lane < KTOP) { s_v[w][lane] = Lv; s_i[w][lane] = Li; }
    __syncwarp();

    // exact merge of local list with (mn, M[0..19])
    if (lane == 0) {
        int* dst = g_idx + (size_t)gw * KTOP;
        int pa = 0, pb = 0;
        #pragma unroll
        for (int r = 0; r < KTOP; ++r) {
            float va = s_v[w][pa]; int ia = s_i[w][pa];
            int   ib = s_M[pb];
            float vb = (ib == 0x7fffffff) ? NEG : mn;
            bool tA = (va > vb) || (va == vb && ia < ib);
            dst[r] = tA ? ia : ib;
            if (tA) ++pa; else ++pb;
        }
    }
}

// ---------------------------------------------------------------------------
// attn v1.1: identical math/association to v1 (bitwise-same output); the only
// change is float4 smem loads in the score loop (FMA order c ascending kept)
// -> 4x fewer LDS ops on the LDS-bound hot loop.
// ---------------------------------------------------------------------------
__global__ void __launch_bounds__(128) attn_kernel() {
    __shared__ __align__(16) float s_knn[4][KTOP][68];
    __shared__ float s_sc [4][KTOP][21];
    __shared__ float s_w  [4][KTOP];
    __shared__ int   s_id [4][KTOP];

    int w = threadIdx.x >> 5, lane = threadIdx.x & 31;
    int p = blockIdx.x * 4 + w;
    int b = p >> 12;

    if (lane < KTOP) s_id[w][lane] = g_idx[p * KTOP + lane];
    __syncwarp();

    for (int r = 0; r < KTOP; ++r) {
        int id = s_id[w][r];
        const float* src = g_xt + ((size_t)(b * NN + id)) * CC;
        s_knn[w][r][lane]      = src[lane];
        s_knn[w][r][lane + 32] = src[lane + 32];
    }
    __syncwarp();

    const float scale = 0.125f;   // 1/sqrt(64)
    for (int t = 0; t < 13; ++t) {
        int q = lane + t * 32;
        if (q < KTOP * KTOP) {
            int i = q / KTOP, j = q % KTOP;
            float s = 0.f;
            #pragma unroll
            for (int c = 0; c < CC; c += 4) {
                float4 xa = *(const float4*)&s_knn[w][i][c];
                float4 xv = *(const float4*)&s_knn[w][j][c];
                s = fmaf(xa.x, xv.x, s);
                s = fmaf(xa.y, xv.y, s);
                s = fmaf(xa.z, xv.z, s);
                s = fmaf(xa.w, xv.w, s);
            }
            s_sc[w][i][j] = s * scale;
        }
    }
    __syncwarp();

    if (lane < KTOP) {
        float m = NEG;
        #pragma unroll
        for (int j = 0; j < KTOP; ++j) m = fmaxf(m, s_sc[w][lane][j]);
        float e[KTOP];
        float sum = 0.f;
        #pragma unroll
        for (int j = 0; j < KTOP; ++j) { e[j] = expf(s_sc[w][lane][j] - m); sum += e[j]; }
        float inv = 1.f / sum;
        #pragma unroll
        for (int j = 0; j < KTOP; ++j) s_sc[w][lane][j] = e[j] * inv;
    }
    __syncwarp();

    if (lane < KTOP) {
        float a = 0.f;
        #pragma unroll
        for (int i = 0; i < KTOP; ++i) a += s_sc[w][i][lane];
        s_w[w][lane] = a * (1.f / (float)KTOP);
    }
    __syncwarp();

    float acc0 = 0.f, acc1 = 0.f;
    #pragma unroll
    for (int j = 0; j < KTOP; ++j) {
        float wj = s_w[w][j];
        acc0 = fmaf(wj, s_knn[w][j][lane],      acc0);
        acc1 = fmaf(wj, s_knn[w][j][lane + 32], acc1);
    }
    g_att[(size_t)p * CC + lane]      = acc0;
    g_att[(size_t)p * CC + lane + 32] = acc1;
}

// ---------------------------------------------------------------------------
// Feature assembly v2 (proven): block = 64 points, att gathers staged through
// smem in 8-channel chunks, fully-coalesced contiguous stores.
// ---------------------------------------------------------------------------
__global__ void __launch_bounds__(256) feat_kernel(const float* __restrict__ x,
                                                   float* __restrict__ out) {
    __shared__ int   s_nb[64 * KTOP];       // 5 KB
    __shared__ float s_att[64 * KTOP][8];   // 40 KB
    __shared__ float s_x[8][64];            // 2 KB

    int b  = blockIdx.y;
    int n0 = blockIdx.x << 6;
    int tid = threadIdx.x;

    for (int e = tid; e < 64 * KTOP; e += 256)
        s_nb[e] = g_idx[((size_t)(b * NN + n0)) * KTOP + e];
    __syncthreads();

    const float* attb = g_att + (size_t)b * NN * CC;
    const float* xb   = x + (size_t)b * CC * NN;
    const size_t outb = ((size_t)b * 2 * CC) * NN * KTOP;

    for (int c0 = 0; c0 < 2 * CC; c0 += 8) {
        __syncthreads();                      // prev chunk readers done
        bool firstHalf = (c0 < CC);
        int cx = firstHalf ? c0 : (c0 - CC);
        for (int e = tid; e < 8 * 64; e += 256) {
            int r = e >> 6, p = e & 63;
            s_x[r][p] = xb[(size_t)(cx + r) * NN + n0 + p];
        }
        if (firstHalf) {
            for (int e = tid; e < 64 * KTOP; e += 256) {
                int nb = s_nb[e];
                const float* src = attb + (size_t)nb * CC + c0;
                *(float4*)&s_att[e][0] = *(const float4*)(src);
                *(float4*)&s_att[e][4] = *(const float4*)(src + 4);
            }
        }
        __syncthreads();
        #pragma unroll
        for (int cc = 0; cc < 8; ++cc) {
            int c2 = c0 + cc;
            float* dst = out + outb + ((size_t)c2 * NN + n0) * KTOP;
            for (int e = tid; e < 64 * KTOP; e += 256) {
                int dn = e / KTOP;
                float v = firstHalf ? (s_att[e][cc] - s_x[cc][dn]) : s_x[cc][dn];
                dst[e] = v;
            }
        }
    }

    // idx_flat tail
    const size_t FEAT = (size_t)BB * 2 * CC * NN * KTOP;
    for (int e = tid; e < 64 * KTOP; e += 256)
        out[FEAT + ((size_t)(b * NN + n0)) * KTOP + e] = (float)(s_nb[e] + b * NN);
}

// ---------------------------------------------------------------------------
extern "C" void kernel_launch(void* const* d_in, const int* in_sizes, int n_in,
                              void* d_out, int out_size) {
    (void)in_sizes; (void)n_in; (void)out_size;
    const float* x  = (const float*)d_in[0];
    const void* loc = d_in[1];          // bool mask (packing auto-detected)
    float* out = (float*)d_out;

    // 5 launches; attn sits 4th (the empirically-captured profiler slot).
    pre_kernel<<<2048 + 1 + 1024, 256>>>(x, (const unsigned char*)loc);
    gemm_kernel<<<dim3(NN / 128, NN / 128, BB), 256>>>(x);
    topk_kernel<<<(BB * NN) / 8, 256>>>(loc);
    attn_kernel<<<(BB * NN) / 4, 128>>>();
    feat_kernel<<<dim3(NN / 64, BB), 256>>>(x, out);
}

// round 14
// speedup vs baseline: 4.8939x; 1.0390x over previous
#include <cuda_runtime.h>

#define BB 4
#define CC 64
#define NN 4096
#define KTOP 20
#define NEG (-3.402823466e38f)

// ---- scratch (static __device__ globals; runtime allocation is forbidden) ----
__device__ float g_xt[BB * NN * CC];                 // (B,N,C)  4 MB
__device__ float g_sq[BB * NN];                      // ||x||^2
__device__ float g_pd[(size_t)BB * NN * NN];         // pairwise "distance" 268 MB
__device__ int   g_idx[BB * NN * KTOP];              // top-k indices
__device__ float g_att[BB * NN * CC];                // attention output (B,N,C)
__device__ int   g_M[BB * KTOP];                     // 20 smallest non-local idx per batch
__device__ int   g_boolmode;                         // 0 = 1-byte bool, 1 = int32

// ---------------------------------------------------------------------------
// pre_kernel: sq (blocks 0..2047) + prep (block 2048).
// ---------------------------------------------------------------------------
__global__ void __launch_bounds__(256) pre_kernel(const float* __restrict__ x,
                                                  const unsigned char* __restrict__ loc) {
    __shared__ int s;
    int blk = blockIdx.x;
    int tid = threadIdx.x;

    if (blk < 2048) {
        // ---- sq role: FROZEN XLA column-reduce tree ----
        int gw   = (blk * 256 + tid) >> 5;
        int lane = tid & 31;
        int b = gw >> 12;
        int n = gw & (NN - 1);
        const float* xb = x + (size_t)b * CC * NN + n;
        float v0 = xb[(size_t)lane * NN];
        float v1 = xb[(size_t)(lane + 32) * NN];
        float p  = __fadd_rn(__fmul_rn(v0, v0), __fmul_rn(v1, v1));
        p = __fadd_rn(p, __shfl_down_sync(0xffffffffu, p, 16));
        p = __fadd_rn(p, __shfl_down_sync(0xffffffffu, p, 8));
        p = __fadd_rn(p, __shfl_down_sync(0xffffffffu, p, 4));
        p = __fadd_rn(p, __shfl_down_sync(0xffffffffu, p, 2));
        p = __fadd_rn(p, __shfl_down_sync(0xffffffffu, p, 1));
        if (lane == 0) g_sq[gw] = p;
    } else {
        // ---- prep role: detect bool packing + per-batch M-list ----
        if (tid == 0) s = 0;
        __syncthreads();
        int any = 0;
        for (int i = tid; i < BB * NN; i += 256)
            if ((i & 3) != 0 && loc[i] != 0) any = 1;
        if (any) atomicOr(&s, 1);
        __syncthreads();
        int mode = s ? 0 : 1;                        // 1 = int32 layout
        if (tid == 0) g_boolmode = mode;

        int b = tid >> 5, lane = tid & 31;
        if (b < BB) {
            const unsigned char* loc8  = loc + b * NN;
            const int*           loc32 = (const int*)loc + b * NN;
            if (lane < KTOP) g_M[b * KTOP + lane] = 0x7fffffff;
            __syncwarp();
            int count = 0;
            for (int base = 0; base < NN && count < KTOP; base += 32) {
                int j = base + lane;
                bool nl = mode ? (loc32[j] == 0) : (loc8[j] == 0);
                unsigned bal = __ballot_sync(0xffffffffu, nl);
                if (nl) {
                    int pos = __popc(bal & ((1u << lane) - 1));
                    if (count + pos < KTOP) g_M[b * KTOP + count + pos] = j;
                }
                count += __popc(bal);
            }
        }
    }
}

// ---------------------------------------------------------------------------
// Transpose x (B,C,N) -> g_xt (B,N,C).
// ---------------------------------------------------------------------------
__global__ void transpose_kernel(const float* __restrict__ x) {
    __shared__ float tile[32][33];
    int b = blockIdx.z, c0 = blockIdx.y * 32, n0 = blockIdx.x * 32;
    #pragma unroll
    for (int i = threadIdx.y; i < 32; i += 8)
        tile[i][threadIdx.x] =
            x[((size_t)(b * CC + c0 + i)) * NN + n0 + threadIdx.x];
    __syncthreads();
    #pragma unroll
    for (int i = threadIdx.y; i < 32; i += 8)
        g_xt[((size_t)(b * NN + n0 + i)) * CC + c0 + threadIdx.x] =
            tile[threadIdx.x][i];
}

// ---------------------------------------------------------------------------
// Pairwise distance GEMM — R4-proven kernel (186us, fma 62%). FROZEN numerics.
// ---------------------------------------------------------------------------
__global__ void __launch_bounds__(256) gemm_kernel(const float* __restrict__ x) {
    __shared__ float As[32][128];
    __shared__ float Bs[32][128];
    int b  = blockIdx.z;
    int ib = blockIdx.y << 7;
    int jb = blockIdx.x << 7;
    int tid = threadIdx.x;
    int tx = tid & 15, ty = tid >> 4;

    const float* xb = x + (size_t)b * CC * NN;

    float acc[8][8];
    #pragma unroll
    for (int i = 0; i < 8; ++i)
        #pragma unroll
        for (int j = 0; j < 8; ++j) acc[i][j] = 0.f;

    for (int k0 = 0; k0 < CC; k0 += 32) {
        if (k0) __syncthreads();
        #pragma unroll
        for (int u = 0; u < 4; ++u) {
            int idx = tid + (u << 8);
            int c = idx >> 5;
            int p = (idx & 31) << 2;
            *(float4*)&As[c][p] = *(const float4*)&xb[(size_t)(k0 + c) * NN + ib + p];
            *(float4*)&Bs[c][p] = *(const float4*)&xb[(size_t)(k0 + c) * NN + jb + p];
        }
        __syncthreads();
        #pragma unroll
        for (int kk = 0; kk < 32; ++kk) {
            float4 a0 = *(float4*)&As[kk][(ty << 2)];
            float4 a1 = *(float4*)&As[kk][64 + (ty << 2)];
            float4 b0 = *(float4*)&Bs[kk][(tx << 2)];
            float4 b1 = *(float4*)&Bs[kk][64 + (tx << 2)];
            float a[8]  = {a0.x, a0.y, a0.z, a0.w, a1.x, a1.y, a1.z, a1.w};
            float bv[8] = {b0.x, b0.y, b0.z, b0.w, b1.x, b1.y, b1.z, b1.w};
            #pragma unroll
            for (int i = 0; i < 8; ++i)
                #pragma unroll
                for (int j = 0; j < 8; ++j)
                    acc[i][j] = fmaf(a[i], bv[j], acc[i][j]);
        }
    }

    int irow[8], jcol[8];
    #pragma unroll
    for (int i = 0; i < 8; ++i)
        irow[i] = ib + ((i < 4) ? (ty << 2) + i : 64 + (ty << 2) + (i - 4));
    #pragma unroll
    for (int j = 0; j < 8; ++j)
        jcol[j] = jb + ((j < 4) ? (tx << 2) + j : 64 + (tx << 2) + (j - 4));

    float sqi[8], sqj[8];
    #pragma unroll
    for (int i = 0; i < 8; ++i) sqi[i] = g_sq[b * NN + irow[i]];
    #pragma unroll
    for (int j = 0; j < 8; ++j) sqj[j] = g_sq[b * NN + jcol[j]];

    #pragma unroll
    for (int i = 0; i < 8; ++i) {
        float* dst = g_pd + ((size_t)(b * NN + irow[i])) * NN;
        float4 v0, v1;
        v0.x = __fsub_rn(__fsub_rn(__fmul_rn(2.f, acc[i][0]), sqi[i]), sqj[0]);
        v0.y = __fsub_rn(__fsub_rn(__fmul_rn(2.f, acc[i][1]), sqi[i]), sqj[1]);
        v0.z = __fsub_rn(__fsub_rn(__fmul_rn(2.f, acc[i][2]), sqi[i]), sqj[2]);
        v0.w = __fsub_rn(__fsub_rn(__fmul_rn(2.f, acc[i][3]), sqi[i]), sqj[3]);
        v1.x = __fsub_rn(__fsub_rn(__fmul_rn(2.f, acc[i][4]), sqi[i]), sqj[4]);
        v1.y = __fsub_rn(__fsub_rn(__fmul_rn(2.f, acc[i][5]), sqi[i]), sqj[5]);
        v1.z = __fsub_rn(__fsub_rn(__fmul_rn(2.f, acc[i][6]), sqi[i]), sqj[6]);
        v1.w = __fsub_rn(__fsub_rn(__fmul_rn(2.f, acc[i][7]), sqi[i]), sqj[7]);
        *(float4*)&dst[jcol[0]] = v0;
        *(float4*)&dst[jcol[4]] = v1;
    }
}

// ---------------------------------------------------------------------------
// topk v3.1 (proven in R12's 510us pass; profiler slot 4).
// ---------------------------------------------------------------------------
__global__ void __launch_bounds__(256) topk_kernel(const void* __restrict__ locraw) {
    __shared__ unsigned s_mask[128];
    __shared__ float s_v[8][KTOP];
    __shared__ int   s_i[8][KTOP];
    __shared__ int   s_M[KTOP];

    int tid  = threadIdx.x;
    int w    = tid >> 5;
    int lane = tid & 31;
    int gw   = blockIdx.x * 8 + w;              // row id; all rows same batch
    int b    = gw >> 12;

    int mode = g_boolmode;
    {
        const unsigned char* loc8  = (const unsigned char*)locraw + b * NN;
        const int*           loc32 = (const int*)locraw + b * NN;
        #pragma unroll
        for (int k = 0; k < 16; ++k) {          // 256 cols per pass
            int col = k * 256 + tid;
            bool lc = mode ? (loc32[col] != 0) : (loc8[col] != 0);
            unsigned word = __ballot_sync(0xffffffffu, lc);
            if (lane == 0) s_mask[k * 8 + w] = word;
        }
    }
    if (tid < KTOP) s_M[tid] = g_M[b * KTOP + tid];
    __syncthreads();

    const float4* row4 = (const float4*)(g_pd + (size_t)gw * NN);

    float Lv = NEG;  int Li = -1;               // list slot; sentinel idx -1
    float thv = NEG; int thi = -1;              // 20th element (threshold)
    float mn = 3.402823466e38f;

    for (int t = 0; t < 32; ++t) {
        float4 vv = row4[t * 32 + lane];
        mn = fminf(mn, fminf(fminf(vv.x, vv.y), fminf(vv.z, vv.w)));
        unsigned wrd = s_mask[t * 4 + (lane >> 3)];
        unsigned nib = (wrd >> ((lane & 7) << 2)) & 0xFu;
        float c0 = (nib & 1u) ? vv.x : NEG;
        float c1 = (nib & 2u) ? vv.y : NEG;
        float c2 = (nib & 4u) ? vv.z : NEG;
        float c3 = (nib & 8u) ? vv.w : NEG;
        float m4 = fmaxf(fmaxf(c0, c1), fmaxf(c2, c3));
        unsigned cand = __ballot_sync(0xffffffffu, m4 >= thv);
        while (cand) {
            int src = __ffs(cand) - 1;
            cand &= cand - 1u;
            float b0 = __shfl_sync(0xffffffffu, c0, src);
            float b1 = __shfl_sync(0xffffffffu, c1, src);
            float b2 = __shfl_sync(0xffffffffu, c2, src);
            float b3 = __shfl_sync(0xffffffffu, c3, src);
            int jb = t * 128 + src * 4;
            #pragma unroll
            for (int e = 0; e < 4; ++e) {
                float cv = (e == 0) ? b0 : (e == 1) ? b1 : (e == 2) ? b2 : b3;
                int   cj = jb + e;
                if (cv > thv || (cv == thv && cj < thi)) {   // warp-uniform
                    bool beats = (cv > Lv) || (cv == Lv && cj < Li);
                    unsigned bb = __ballot_sync(0xffffffffu, beats) & 0xFFFFFu;
                    int pos = __ffs(bb) - 1;    // >=0: beats true at lane 19
                    float pv = __shfl_up_sync(0xffffffffu, Lv, 1);
                    int   pi = __shfl_up_sync(0xffffffffu, Li, 1);
                    if (lane > pos)  { Lv = pv; Li = pi; }
                    if (lane == pos) { Lv = cv; Li = cj; }
                    thv = __shfl_sync(0xffffffffu, Lv, KTOP - 1);
                    thi = __shfl_sync(0xffffffffu, Li, KTOP - 1);
                }
            }
            if (cand)                            // drop stale candidates
                cand = __ballot_sync(0xffffffffu,
                                     ((cand >> lane) & 1u) && (m4 >= thv));
        }
    }
    #pragma unroll
    for (int o = 16; o; o >>= 1)
        mn = fminf(mn, __shfl_xor_sync(0xffffffffu, mn, o));

    if (lane < KTOP) { s_v[w][lane] = Lv; s_i[w][lane] = Li; }
    __syncwarp();

    // exact merge of local list with (mn, M[0..19])
    if (lane == 0) {
        int* dst = g_idx + (size_t)gw * KTOP;
        int pa = 0, pb = 0;
        #pragma unroll
        for (int r = 0; r < KTOP; ++r) {
            float va = s_v[w][pa]; int ia = s_i[w][pa];
            int   ib = s_M[pb];
            float vb = (ib == 0x7fffffff) ? NEG : mn;
            bool tA = (va > vb) || (va == vb && ia < ib);
            dst[r] = tA ? ia : ib;
            if (tA) ++pa; else ++pb;
        }
    }
}

// ---------------------------------------------------------------------------
// attn v1.2b: symmetry (s[i][j]=s[j][i] bitwise), FIXED triangle decode.
// Row r+1 of the upper triangle starts at closed-form
//   base_{r+1} = (r+1)*KTOP - r*(r+1)/2   (independent of loop state —
// the R13 bug was accumulating this from a conditionally-updated base).
// Verified: q=19 -> (0,19); q=20 -> (1,1); q=209 -> (19,19).
// ---------------------------------------------------------------------------
__global__ void __launch_bounds__(128) attn_kernel() {
    __shared__ __align__(16) float s_knn[4][KTOP][68];
    __shared__ float s_sc [4][KTOP][21];
    __shared__ float s_w  [4][KTOP];
    __shared__ int   s_id [4][KTOP];

    int w = threadIdx.x >> 5, lane = threadIdx.x & 31;
    int p = blockIdx.x * 4 + w;
    int b = p >> 12;

    if (lane < KTOP) s_id[w][lane] = g_idx[p * KTOP + lane];
    __syncwarp();

    for (int r = 0; r < KTOP; ++r) {
        int id = s_id[w][r];
        const float* src = g_xt + ((size_t)(b * NN + id)) * CC;
        s_knn[w][r][lane]      = src[lane];
        s_knn[w][r][lane + 32] = src[lane + 32];
    }
    __syncwarp();

    const float scale = 0.125f;   // 1/sqrt(64)
    #pragma unroll
    for (int t = 0; t < 7; ++t) {
        int q = lane + t * 32;
        if (q < 210) {
            // decode upper-triangle (i<=j): closed-form row starts
            int i = 0, base = 0;
            #pragma unroll
            for (int r = 0; r < KTOP - 1; ++r) {
                int nb = (r + 1) * KTOP - (r * (r + 1)) / 2;  // start of row r+1
                if (q >= nb) { base = nb; i = r + 1; }
            }
            int j = i + (q - base);
            float s = 0.f;
            #pragma unroll
            for (int c = 0; c < CC; c += 4) {
                float4 xa = *(const float4*)&s_knn[w][i][c];
                float4 xv = *(const float4*)&s_knn[w][j][c];
                s = fmaf(xa.x, xv.x, s);
                s = fmaf(xa.y, xv.y, s);
                s = fmaf(xa.z, xv.z, s);
                s = fmaf(xa.w, xv.w, s);
            }
            float sv = s * scale;
            s_sc[w][i][j] = sv;
            s_sc[w][j][i] = sv;     // bitwise-identical to direct computation
        }
    }
    __syncwarp();

    if (lane < KTOP) {
        float m = NEG;
        #pragma unroll
        for (int j = 0; j < KTOP; ++j) m = fmaxf(m, s_sc[w][lane][j]);
        float e[KTOP];
        float sum = 0.f;
        #pragma unroll
        for (int j = 0; j < KTOP; ++j) { e[j] = expf(s_sc[w][lane][j] - m); sum += e[j]; }
        float inv = 1.f / sum;
        #pragma unroll
        for (int j = 0; j < KTOP; ++j) s_sc[w][lane][j] = e[j] * inv;
    }
    __syncwarp();

    if (lane < KTOP) {
        float a = 0.f;
        #pragma unroll
        for (int i = 0; i < KTOP; ++i) a += s_sc[w][i][lane];
        s_w[w][lane] = a * (1.f / (float)KTOP);
    }
    __syncwarp();

    float acc0 = 0.f, acc1 = 0.f;
    #pragma unroll
    for (int j = 0; j < KTOP; ++j) {
        float wj = s_w[w][j];
        acc0 = fmaf(wj, s_knn[w][j][lane],      acc0);
        acc1 = fmaf(wj, s_knn[w][j][lane + 32], acc1);
    }
    g_att[(size_t)p * CC + lane]      = acc0;
    g_att[(size_t)p * CC + lane + 32] = acc1;
}

// ---------------------------------------------------------------------------
// Feature assembly v2 (proven): block = 64 points, att gathers staged through
// smem in 8-channel chunks, fully-coalesced contiguous stores.
// ---------------------------------------------------------------------------
__global__ void __launch_bounds__(256) feat_kernel(const float* __restrict__ x,
                                                   float* __restrict__ out) {
    __shared__ int   s_nb[64 * KTOP];       // 5 KB
    __shared__ float s_att[64 * KTOP][8];   // 40 KB
    __shared__ float s_x[8][64];            // 2 KB

    int b  = blockIdx.y;
    int n0 = blockIdx.x << 6;
    int tid = threadIdx.x;

    for (int e = tid; e < 64 * KTOP; e += 256)
        s_nb[e] = g_idx[((size_t)(b * NN + n0)) * KTOP + e];
    __syncthreads();

    const float* attb = g_att + (size_t)b * NN * CC;
    const float* xb   = x + (size_t)b * CC * NN;
    const size_t outb = ((size_t)b * 2 * CC) * NN * KTOP;

    for (int c0 = 0; c0 < 2 * CC; c0 += 8) {
        __syncthreads();                      // prev chunk readers done
        bool firstHalf = (c0 < CC);
        int cx = firstHalf ? c0 : (c0 - CC);
        for (int e = tid; e < 8 * 64; e += 256) {
            int r = e >> 6, p = e & 63;
            s_x[r][p] = xb[(size_t)(cx + r) * NN + n0 + p];
        }
        if (firstHalf) {
            for (int e = tid; e < 64 * KTOP; e += 256) {
                int nb = s_nb[e];
                const float* src = attb + (size_t)nb * CC + c0;
                *(float4*)&s_att[e][0] = *(const float4*)(src);
                *(float4*)&s_att[e][4] = *(const float4*)(src + 4);
            }
        }
        __syncthreads();
        #pragma unroll
        for (int cc = 0; cc < 8; ++cc) {
            int c2 = c0 + cc;
            float* dst = out + outb + ((size_t)c2 * NN + n0) * KTOP;
            for (int e = tid; e < 64 * KTOP; e += 256) {
                int dn = e / KTOP;
                float v = firstHalf ? (s_att[e][cc] - s_x[cc][dn]) : s_x[cc][dn];
                dst[e] = v;
            }
        }
    }

    // idx_flat tail
    const size_t FEAT = (size_t)BB * 2 * CC * NN * KTOP;
    for (int e = tid; e < 64 * KTOP; e += 256)
        out[FEAT + ((size_t)(b * NN + n0)) * KTOP + e] = (float)(s_nb[e] + b * NN);
}

// ---------------------------------------------------------------------------
extern "C" void kernel_launch(void* const* d_in, const int* in_sizes, int n_in,
                              void* d_out, int out_size) {
    (void)in_sizes; (void)n_in; (void)out_size;
    const float* x  = (const float*)d_in[0];
    const void* loc = d_in[1];          // bool mask (packing auto-detected)
    float* out = (float*)d_out;

    // 6 launches; topk sits 4th (the empirically-captured profiler slot).
    pre_kernel<<<2048 + 1, 256>>>(x, (const unsigned char*)loc);
    gemm_kernel<<<dim3(NN / 128, NN / 128, BB), 256>>>(x);
    transpose_kernel<<<dim3(NN / 32, CC / 32, BB), dim3(32, 8)>>>(x);
    topk_kernel<<<(BB * NN) / 8, 256>>>(loc);
    attn_kernel<<<(BB * NN) / 4, 128>>>();
    feat_kernel<<<dim3(NN / 64, BB), 256>>>(x, out);
}